// round 2
// baseline (speedup 1.0000x reference)
#include <cuda_runtime.h>
#include <math.h>

#define N_SAMP 2048
#define DD 784          // DIM*DIM
#define KR 10
#define LAYERS 32
#define KCLS 10
#define HCONST 0.001f

// ---------------- scratch (static device globals; no allocation) ------------
__device__ float g_s[N_SAMP * KR * KR];   // evolving 10x10 core per sample
__device__ float g_x[N_SAMP * DD];        // current x = u s vh per sample
__device__ float g_z[N_SAMP * DD];        // Z = x @ W^T per layer

// ---------------- init: parse X -> (u,s,vh), x = u s vh ---------------------
__global__ void init_kernel(const float* __restrict__ X) {
    __shared__ float u[280], vh[280], s[100], US[280];
    int i = blockIdx.x, t = threadIdx.x;
    const float* xb = X + (size_t)i * 840;
    for (int k = t; k < 280; k += blockDim.x) { u[k] = xb[k]; vh[k] = xb[560 + k]; }
    for (int k = t; k < 100; k += blockDim.x) { float v = xb[280 + k]; s[k] = v; g_s[i * 100 + k] = v; }
    __syncthreads();
    // US = u @ s  (28x10)
    for (int k = t; k < 280; k += blockDim.x) {
        int r = k / 10, b = k % 10;
        float acc = 0.f;
#pragma unroll
        for (int a = 0; a < 10; a++) acc += u[r * 10 + a] * s[a * 10 + b];
        US[k] = acc;
    }
    __syncthreads();
    // x = US @ vh  (28x28)
    for (int k = t; k < DD; k += blockDim.x) {
        int r = k / 28, c = k % 28;
        float acc = 0.f;
#pragma unroll
        for (int b = 0; b < 10; b++) acc += US[r * 10 + b] * vh[b * 28 + c];
        g_x[(size_t)i * DD + k] = acc;
    }
}

// ---------------- GEMM: g_z = g_x @ W^T  (2048x784 x 784x784) ---------------
#define BM 64
#define BN 64
#define BK 16

__global__ __launch_bounds__(256) void gemm_kernel(const float* __restrict__ W) {
    __shared__ float As[BK][BM + 1];
    __shared__ float Bs[BK][BN + 1];
    const float* A = g_x;
    float* C = g_z;
    int bm = blockIdx.y * BM;
    int bn = blockIdx.x * BN;
    int tid = threadIdx.x;
    int tx = tid & 15, ty = tid >> 4;
    float acc[4][4] = {};
    int ar = tid >> 2;             // 0..63
    int ak = (tid & 3) << 2;       // 0,4,8,12
    const float* Aptr = A + (size_t)(bm + ar) * DD + ak;
    int brow = bn + ar;
    const float* Bptr = W + (size_t)brow * DD + ak;
    bool bok = (brow < DD);
    for (int k0 = 0; k0 < DD; k0 += BK) {
        float4 av = *(const float4*)(Aptr + k0);
        As[ak + 0][ar] = av.x; As[ak + 1][ar] = av.y; As[ak + 2][ar] = av.z; As[ak + 3][ar] = av.w;
        float4 bv = bok ? *(const float4*)(Bptr + k0) : make_float4(0.f, 0.f, 0.f, 0.f);
        Bs[ak + 0][ar] = bv.x; Bs[ak + 1][ar] = bv.y; Bs[ak + 2][ar] = bv.z; Bs[ak + 3][ar] = bv.w;
        __syncthreads();
#pragma unroll
        for (int k = 0; k < BK; k++) {
            float ra[4], rb[4];
#pragma unroll
            for (int m = 0; m < 4; m++) ra[m] = As[k][ty * 4 + m];
#pragma unroll
            for (int n = 0; n < 4; n++) rb[n] = Bs[k][tx * 4 + n];
#pragma unroll
            for (int m = 0; m < 4; m++)
#pragma unroll
                for (int n = 0; n < 4; n++) acc[m][n] += ra[m] * rb[n];
        }
        __syncthreads();
    }
#pragma unroll
    for (int m = 0; m < 4; m++) {
        int row = bm + ty * 4 + m;
#pragma unroll
        for (int n = 0; n < 4; n++) {
            int col = bn + tx * 4 + n;
            if (col < DD) C[(size_t)row * DD + col] = acc[m][n];
        }
    }
}

// ---------------- update: dY=relu(Z+b); s += H u^T dY v; x = u s vh ---------
__global__ void update_kernel(const float* __restrict__ X, const float* __restrict__ bias,
                              int do_relu, float* __restrict__ trans, int col) {
    __shared__ float u[280], vh[280], s[100], dY[DD], P[280], US[280];
    int i = blockIdx.x, t = threadIdx.x;
    const float* xb = X + (size_t)i * 840;
    for (int k = t; k < 280; k += blockDim.x) { u[k] = xb[k]; vh[k] = xb[560 + k]; }
    for (int k = t; k < 100; k += blockDim.x) s[k] = g_s[i * 100 + k];
    for (int k = t; k < DD; k += blockDim.x) {
        float z = g_z[(size_t)i * DD + k];
        if (bias) z += bias[k];
        if (do_relu) z = fmaxf(z, 0.f);
        dY[k] = z;
    }
    __syncthreads();
    // P = u^T dY  (10x28): P[a][c] = sum_r u[r][a] dY[r][c]
    for (int k = t; k < 280; k += blockDim.x) {
        int a = k / 28, c = k % 28;
        float acc = 0.f;
#pragma unroll
        for (int r = 0; r < 28; r++) acc += u[r * 10 + a] * dY[r * 28 + c];
        P[k] = acc;
    }
    __syncthreads();
    // dS[a][b] = sum_c P[a][c] vh[b][c];  s += H dS
    for (int k = t; k < 100; k += blockDim.x) {
        int a = k / 10, b = k % 10;
        float acc = 0.f;
#pragma unroll
        for (int c = 0; c < 28; c++) acc += P[a * 28 + c] * vh[b * 28 + c];
        float sn = s[k] + HCONST * acc;
        s[k] = sn;
        g_s[i * 100 + k] = sn;
    }
    __syncthreads();
    // US = u @ s
    for (int k = t; k < 280; k += blockDim.x) {
        int r = k / 10, b = k % 10;
        float acc = 0.f;
#pragma unroll
        for (int a = 0; a < 10; a++) acc += u[r * 10 + a] * s[a * 10 + b];
        US[k] = acc;
    }
    __syncthreads();
    // x = US @ vh ; write to g_x and X_transformed[:, :, col]
    for (int k = t; k < DD; k += blockDim.x) {
        int r = k / 28, c = k % 28;
        float acc = 0.f;
#pragma unroll
        for (int b = 0; b < 10; b++) acc += US[r * 10 + b] * vh[b * 28 + c];
        g_x[(size_t)i * DD + k] = acc;
        trans[(size_t)i * (DD * 33) + (size_t)k * 33 + col] = acc;
    }
}

// ---------------- classify: logits = x Wc^T + bc ; softmax ------------------
__global__ void classify_kernel(const float* __restrict__ Wc, const float* __restrict__ bc,
                                float* __restrict__ pred, float* __restrict__ cls) {
    int i = blockIdx.x, lane = threadIdx.x;  // 32 threads
    const float* x = g_x + (size_t)i * DD;
    float xv[25];
#pragma unroll
    for (int k = 0; k < 25; k++) {
        int j = lane + 32 * k;
        xv[k] = (j < DD) ? x[j] : 0.f;
    }
    float lg[KCLS];
#pragma unroll
    for (int c = 0; c < KCLS; c++) {
        const float* w = Wc + (size_t)c * DD;
        float acc = 0.f;
#pragma unroll
        for (int k = 0; k < 25; k++) {
            int j = lane + 32 * k;
            acc += (j < DD) ? xv[k] * w[j] : 0.f;
        }
#pragma unroll
        for (int o = 16; o; o >>= 1) acc += __shfl_down_sync(0xffffffffu, acc, o);
        lg[c] = acc;
    }
    if (lane == 0) {
        float mx = -1e30f;
#pragma unroll
        for (int c = 0; c < KCLS; c++) {
            lg[c] += bc[c];
            cls[(size_t)i * KCLS + c] = lg[c];
            if (lg[c] > mx) mx = lg[c];
        }
        float e[KCLS], ssum = 0.f;
#pragma unroll
        for (int c = 0; c < KCLS; c++) { e[c] = expf(lg[c] - mx); ssum += e[c]; }
        float inv = 1.f / ssum;
#pragma unroll
        for (int c = 0; c < KCLS; c++) pred[(size_t)i * KCLS + c] = e[c] * inv;
    }
}

// ---------------- launcher ---------------------------------------------------
extern "C" void kernel_launch(void* const* d_in, const int* in_sizes, int n_in,
                              void* d_out, int out_size) {
    const float* X  = (const float*)d_in[0];   // (2048, 3, 280)
    const float* W0 = (const float*)d_in[1];   // (784, 784)
    const float* Ws = (const float*)d_in[2];   // (32, 784, 784)
    const float* bs = (const float*)d_in[3];   // (32, 784)
    const float* Wc = (const float*)d_in[4];   // (10, 784)
    const float* bc = (const float*)d_in[5];   // (10)
    float* out = (float*)d_out;
    float* pred  = out;                          // (2048, 10)
    float* cls   = out + (size_t)N_SAMP * KCLS;  // (2048, 10)
    float* trans = out + (size_t)2 * N_SAMP * KCLS; // (2048, 784, 33)

    dim3 ggrid((DD + BN - 1) / BN, N_SAMP / BM);   // (13, 32)

    init_kernel<<<N_SAMP, 256>>>(X);
    gemm_kernel<<<ggrid, 256>>>(W0);
    update_kernel<<<N_SAMP, 256>>>(X, nullptr, 0, trans, 0);
    for (int l = 0; l < LAYERS; l++) {
        gemm_kernel<<<ggrid, 256>>>(Ws + (size_t)l * DD * DD);
        update_kernel<<<N_SAMP, 256>>>(X, bs + (size_t)l * DD, 1, trans, l + 1);
    }
    classify_kernel<<<N_SAMP, 32>>>(Wc, bc, pred, cls);
}

// round 4
// speedup vs baseline: 2.2555x; 2.2555x over previous
#include <cuda_runtime.h>
#include <cuda_bf16.h>
#include <cstdint>
#include <math.h>

#define N_SAMP 2048
#define DD 784
#define KR 10
#define LAYERS 32
#define KCLS 10
#define HCONST 0.001f

__device__ float g_s[N_SAMP * KR * KR];
__device__ __nv_bfloat16 g_xh[N_SAMP * DD];
__device__ float g_z[N_SAMP * DD];
__device__ __nv_bfloat16 g_wh[33 * DD * DD];
__device__ float g_stage[33 * N_SAMP * DD];

__global__ void wcvt_kernel(const float* __restrict__ W0, const float* __restrict__ Ws) {
    size_t idx = ((size_t)blockIdx.x * blockDim.x + threadIdx.x) * 4;
    size_t total = (size_t)33 * DD * DD;
    if (idx >= total) return;
    size_t per = (size_t)DD * DD;
    const float* src = (idx < per) ? (W0 + idx) : (Ws + (idx - per));
    float4 v = *(const float4*)src;
    __nv_bfloat16 o[4] = {__float2bfloat16(v.x), __float2bfloat16(v.y),
                          __float2bfloat16(v.z), __float2bfloat16(v.w)};
    *(uint2*)(g_wh + idx) = *(uint2*)o;
}

__global__ void init_kernel(const float* __restrict__ X) {
    __shared__ float u[280], vh[280], s[100], US[280];
    int i = blockIdx.x, t = threadIdx.x;
    const float* xb = X + (size_t)i * 840;
    for (int k = t; k < 280; k += blockDim.x) { u[k] = xb[k]; vh[k] = xb[560 + k]; }
    for (int k = t; k < 100; k += blockDim.x) { float v = xb[280 + k]; s[k] = v; g_s[i * 100 + k] = v; }
    __syncthreads();
    for (int k = t; k < 280; k += blockDim.x) {
        int r = k / 10, b = k % 10;
        float acc = 0.f;
#pragma unroll
        for (int a = 0; a < 10; a++) acc += u[r * 10 + a] * s[a * 10 + b];
        US[k] = acc;
    }
    __syncthreads();
    for (int k = t; k < DD; k += blockDim.x) {
        int r = k / 28, c = k % 28;
        float acc = 0.f;
#pragma unroll
        for (int b = 0; b < 10; b++) acc += US[r * 10 + b] * vh[b * 28 + c];
        g_xh[(size_t)i * DD + k] = __float2bfloat16(acc);
    }
}

#define GBM 64
#define GBN 112
#define GBK 32
#define SPAD 40

__global__ __launch_bounds__(256) void gemm_tc_kernel(const __nv_bfloat16* __restrict__ W,
                                                      const float* __restrict__ bias,
                                                      int do_relu) {
    __shared__ __nv_bfloat16 As[GBM][SPAD];
    __shared__ __nv_bfloat16 Bs[GBN][SPAD];
    int bm = blockIdx.y * GBM;
    int bn = blockIdx.x * GBN;
    int tid = threadIdx.x;
    int wid = tid >> 5, lane = tid & 31;
    int wm = wid & 3, wn = wid >> 2;
    int g = lane >> 2, tg = lane & 3;

    float acc[7][4] = {};

    for (int k0 = 0; k0 < DD; k0 += GBK) {
#pragma unroll
        for (int it = 0; it < 2; it++) {
            int task = tid + it * 256;
            int row = task >> 3, cg = task & 7;
            int kk = k0 + 4 * cg;
            uint2 v = make_uint2(0u, 0u);
            if (kk < DD) v = *(const uint2*)(g_xh + (size_t)(bm + row) * DD + kk);
            *(uint2*)&As[row][4 * cg] = v;
        }
#pragma unroll
        for (int it = 0; it < 4; it++) {
            int task = tid + it * 256;
            if (task < 896) {
                int row = task >> 3, cg = task & 7;
                int kk = k0 + 4 * cg;
                uint2 v = make_uint2(0u, 0u);
                if (kk < DD) v = *(const uint2*)(W + (size_t)(bn + row) * DD + kk);
                *(uint2*)&Bs[row][4 * cg] = v;
            }
        }
        __syncthreads();
#pragma unroll
        for (int kk = 0; kk < GBK; kk += 16) {
            unsigned int a0 = *(const unsigned int*)&As[wm * 16 + g][kk + 2 * tg];
            unsigned int a1 = *(const unsigned int*)&As[wm * 16 + g + 8][kk + 2 * tg];
            unsigned int a2 = *(const unsigned int*)&As[wm * 16 + g][kk + 2 * tg + 8];
            unsigned int a3 = *(const unsigned int*)&As[wm * 16 + g + 8][kk + 2 * tg + 8];
#pragma unroll
            for (int j = 0; j < 7; j++) {
                int nrow = wn * 56 + j * 8 + g;
                unsigned int b0 = *(const unsigned int*)&Bs[nrow][kk + 2 * tg];
                unsigned int b1 = *(const unsigned int*)&Bs[nrow][kk + 2 * tg + 8];
                asm volatile(
                    "mma.sync.aligned.m16n8k16.row.col.f32.bf16.bf16.f32 "
                    "{%0,%1,%2,%3}, {%4,%5,%6,%7}, {%8,%9}, {%0,%1,%2,%3};"
                    : "+f"(acc[j][0]), "+f"(acc[j][1]), "+f"(acc[j][2]), "+f"(acc[j][3])
                    : "r"(a0), "r"(a1), "r"(a2), "r"(a3), "r"(b0), "r"(b1));
            }
        }
        __syncthreads();
    }
    int row0 = bm + wm * 16 + g;
    int row1 = row0 + 8;
#pragma unroll
    for (int j = 0; j < 7; j++) {
        int col = bn + wn * 56 + j * 8 + 2 * tg;
        float b0 = bias ? bias[col] : 0.f;
        float b1 = bias ? bias[col + 1] : 0.f;
        float2 v0 = make_float2(acc[j][0] + b0, acc[j][1] + b1);
        float2 v1 = make_float2(acc[j][2] + b0, acc[j][3] + b1);
        if (do_relu) {
            v0.x = fmaxf(v0.x, 0.f); v0.y = fmaxf(v0.y, 0.f);
            v1.x = fmaxf(v1.x, 0.f); v1.y = fmaxf(v1.y, 0.f);
        }
        *(float2*)(g_z + (size_t)row0 * DD + col) = v0;
        *(float2*)(g_z + (size_t)row1 * DD + col) = v1;
    }
}

__global__ void update_kernel(const float* __restrict__ X, int col) {
    __shared__ float u[280], vh[280], s[100], dY[DD], P[280], US[280];
    int i = blockIdx.x, t = threadIdx.x;
    const float* xb = X + (size_t)i * 840;
    for (int k = t; k < 280; k += blockDim.x) { u[k] = xb[k]; vh[k] = xb[560 + k]; }
    for (int k = t; k < 100; k += blockDim.x) s[k] = g_s[i * 100 + k];
    for (int k = t; k < DD; k += blockDim.x) dY[k] = g_z[(size_t)i * DD + k];
    __syncthreads();
    for (int k = t; k < 280; k += blockDim.x) {
        int a = k / 28, c = k % 28;
        float acc = 0.f;
#pragma unroll
        for (int r = 0; r < 28; r++) acc += u[r * 10 + a] * dY[r * 28 + c];
        P[k] = acc;
    }
    __syncthreads();
    for (int k = t; k < 100; k += blockDim.x) {
        int a = k / 10, b = k % 10;
        float acc = 0.f;
#pragma unroll
        for (int c = 0; c < 28; c++) acc += P[a * 28 + c] * vh[b * 28 + c];
        float sn = s[k] + HCONST * acc;
        s[k] = sn;
        g_s[i * 100 + k] = sn;
    }
    __syncthreads();
    for (int k = t; k < 280; k += blockDim.x) {
        int r = k / 10, b = k % 10;
        float acc = 0.f;
#pragma unroll
        for (int a = 0; a < 10; a++) acc += u[r * 10 + a] * s[a * 10 + b];
        US[k] = acc;
    }
    __syncthreads();
    float* stg = g_stage + (size_t)col * N_SAMP * DD + (size_t)i * DD;
    for (int k = t; k < DD; k += blockDim.x) {
        int r = k / 28, c = k % 28;
        float acc = 0.f;
#pragma unroll
        for (int b = 0; b < 10; b++) acc += US[r * 10 + b] * vh[b * 28 + c];
        stg[k] = acc;
        g_xh[(size_t)i * DD + k] = __float2bfloat16(acc);
    }
}

__global__ void transpose_kernel(float* __restrict__ trans) {
    size_t idx = (size_t)blockIdx.x * blockDim.x + threadIdx.x;
    if (idx >= (size_t)N_SAMP * DD) return;
    float v[33];
#pragma unroll
    for (int l = 0; l < 33; l++) v[l] = g_stage[(size_t)l * N_SAMP * DD + idx];
    float* o = trans + idx * 33;
#pragma unroll
    for (int l = 0; l < 33; l++) o[l] = v[l];
}

__global__ void classify_kernel(const float* __restrict__ Wc, const float* __restrict__ bc,
                                float* __restrict__ pred, float* __restrict__ cls) {
    int i = blockIdx.x, lane = threadIdx.x;
    const float* x = g_stage + (size_t)32 * N_SAMP * DD + (size_t)i * DD;
    float xv[25];
#pragma unroll
    for (int k = 0; k < 25; k++) {
        int j = lane + 32 * k;
        xv[k] = (j < DD) ? x[j] : 0.f;
    }
    float lg[KCLS];
#pragma unroll
    for (int c = 0; c < KCLS; c++) {
        const float* w = Wc + (size_t)c * DD;
        float acc = 0.f;
#pragma unroll
        for (int k = 0; k < 25; k++) {
            int j = lane + 32 * k;
            acc += (j < DD) ? xv[k] * w[j] : 0.f;
        }
#pragma unroll
        for (int o = 16; o; o >>= 1) acc += __shfl_down_sync(0xffffffffu, acc, o);
        lg[c] = acc;
    }
    if (lane == 0) {
        float mx = -1e30f;
#pragma unroll
        for (int c = 0; c < KCLS; c++) {
            lg[c] += bc[c];
            cls[(size_t)i * KCLS + c] = lg[c];
            if (lg[c] > mx) mx = lg[c];
        }
        float e[KCLS], ssum = 0.f;
#pragma unroll
        for (int c = 0; c < KCLS; c++) { e[c] = expf(lg[c] - mx); ssum += e[c]; }
        float inv = 1.f / ssum;
#pragma unroll
        for (int c = 0; c < KCLS; c++) pred[(size_t)i * KCLS + c] = e[c] * inv;
    }
}

extern "C" void kernel_launch(void* const* d_in, const int* in_sizes, int n_in,
                              void* d_out, int out_size) {
    const float* X  = (const float*)d_in[0];
    const float* W0 = (const float*)d_in[1];
    const float* Ws = (const float*)d_in[2];
    const float* bs = (const float*)d_in[3];
    const float* Wc = (const float*)d_in[4];
    const float* bc = (const float*)d_in[5];
    float* out = (float*)d_out;
    float* pred  = out;
    float* cls   = out + (size_t)N_SAMP * KCLS;
    float* trans = out + (size_t)2 * N_SAMP * KCLS;

    static const __nv_bfloat16* wh_dev = nullptr;
    if (!wh_dev) {
        void* p = nullptr;
        cudaGetSymbolAddress(&p, g_wh);
        wh_dev = (const __nv_bfloat16*)p;
    }

    {
        size_t total = (size_t)33 * DD * DD;
        int blocks = (int)((total / 4 + 255) / 256);
        wcvt_kernel<<<blocks, 256>>>(W0, Ws);
    }
    init_kernel<<<N_SAMP, 256>>>(X);

    dim3 ggrid(DD / GBN, N_SAMP / GBM);   // (7, 32)
    for (int col = 0; col < 33; col++) {
        const __nv_bfloat16* W = wh_dev + (size_t)col * DD * DD;
        const float* bias = (col > 0) ? (bs + (size_t)(col - 1) * DD) : nullptr;
        gemm_tc_kernel<<<ggrid, 256>>>(W, bias, col > 0 ? 1 : 0);
        update_kernel<<<N_SAMP, 256>>>(X, col);
    }
    {
        int total = N_SAMP * DD;
        transpose_kernel<<<(total + 255) / 256, 256>>>(trans);
    }
    classify_kernel<<<N_SAMP, 32>>>(Wc, bc, pred, cls);
}

// round 5
// speedup vs baseline: 3.5169x; 1.5593x over previous
#include <cuda_runtime.h>
#include <cuda_bf16.h>
#include <cstdint>
#include <math.h>

#define N_SAMP 2048
#define DD 784
#define KR 10
#define LAYERS 32
#define KCLS 10
#define HCONST 0.001f

__device__ float g_s[N_SAMP * 100];                 // evolving 10x10 core
__device__ float g_shist[33 * N_SAMP * 100];        // s after each layer (27MB)
__device__ __nv_bfloat16 g_xh[N_SAMP * DD];         // x in bf16 (GEMM A)
__device__ float g_z[N_SAMP * DD];                  // dY
__device__ __nv_bfloat16 g_wh[33 * DD * DD];        // weights bf16

// ---------------- weights -> bf16 -------------------------------------------
__global__ void wcvt_kernel(const float* __restrict__ W0, const float* __restrict__ Ws) {
    size_t idx = ((size_t)blockIdx.x * blockDim.x + threadIdx.x) * 4;
    size_t total = (size_t)33 * DD * DD;
    if (idx >= total) return;
    size_t per = (size_t)DD * DD;
    const float* src = (idx < per) ? (W0 + idx) : (Ws + (idx - per));
    float4 v = *(const float4*)src;
    __nv_bfloat16 o[4] = {__float2bfloat16(v.x), __float2bfloat16(v.y),
                          __float2bfloat16(v.z), __float2bfloat16(v.w)};
    *(uint2*)(g_wh + idx) = *(uint2*)o;
}

// ---------------- init -------------------------------------------------------
__global__ void init_kernel(const float* __restrict__ X) {
    __shared__ float u[280], vh[280], s[100], US[280];
    int i = blockIdx.x, t = threadIdx.x;
    const float* xb = X + (size_t)i * 840;
    for (int k = t; k < 280; k += blockDim.x) { u[k] = xb[k]; vh[k] = xb[560 + k]; }
    for (int k = t; k < 100; k += blockDim.x) { float v = xb[280 + k]; s[k] = v; g_s[i * 100 + k] = v; }
    __syncthreads();
    for (int k = t; k < 280; k += blockDim.x) {
        int r = k / 10, b = k % 10;
        float acc = 0.f;
#pragma unroll
        for (int a = 0; a < 10; a++) acc += u[r * 10 + a] * s[a * 10 + b];
        US[k] = acc;
    }
    __syncthreads();
    for (int k = t; k < DD; k += blockDim.x) {
        int r = k / 28, c = k % 28;
        float acc = 0.f;
#pragma unroll
        for (int b = 0; b < 10; b++) acc += US[r * 10 + b] * vh[b * 28 + c];
        g_xh[(size_t)i * DD + k] = __float2bfloat16(acc);
    }
}

// ---------------- GEMM: g_z = relu(g_xh @ W^T + b) --------------------------
// BM=128, BN=112, BK=32, 256 threads (4x2 warps, warp tile 32x56), cp.async 2-stage
#define GBM 128
#define GBN 112
#define GBK 32
#define SPAD 40
#define NIT 25

__device__ __forceinline__ unsigned smem_u32(const void* p) {
    return (unsigned)__cvta_generic_to_shared(p);
}
__device__ __forceinline__ void cp16(unsigned dst, const void* src, int sz) {
    asm volatile("cp.async.cg.shared.global [%0], [%1], 16, %2;\n"
                 :: "r"(dst), "l"(src), "r"(sz));
}

__global__ __launch_bounds__(256) void gemm_tc_kernel(const __nv_bfloat16* __restrict__ W,
                                                      const float* __restrict__ bias,
                                                      int do_relu) {
    __shared__ __nv_bfloat16 As[2][GBM][SPAD];
    __shared__ __nv_bfloat16 Bs[2][GBN][SPAD];
    int bm = blockIdx.y * GBM;
    int bn = blockIdx.x * GBN;
    int tid = threadIdx.x;
    int wid = tid >> 5, lane = tid & 31;
    int wm = wid & 3, wn = wid >> 2;
    int g = lane >> 2, tg = lane & 3;

    float acc[2][7][4] = {};

    // stage loader
    auto load_stage = [&](int it, int buf) {
        int k0 = it * GBK;
        // A: 128 rows x 4 chunks of 16B
#pragma unroll
        for (int ii = 0; ii < 2; ii++) {
            int task = tid + ii * 256;
            int row = task >> 2, cg = task & 3;
            int kk = k0 + 8 * cg;
            const __nv_bfloat16* src = g_xh + (size_t)(bm + row) * DD + kk;
            cp16(smem_u32(&As[buf][row][8 * cg]), src, (kk < DD) ? 16 : 0);
        }
        // B: 112 rows x 4 chunks
#pragma unroll
        for (int ii = 0; ii < 2; ii++) {
            int task = tid + ii * 256;
            if (task < 448) {
                int row = task >> 2, cg = task & 3;
                int kk = k0 + 8 * cg;
                const __nv_bfloat16* src = W + (size_t)(bn + row) * DD + kk;
                cp16(smem_u32(&Bs[buf][row][8 * cg]), src, (kk < DD) ? 16 : 0);
            }
        }
        asm volatile("cp.async.commit_group;\n");
    };

    load_stage(0, 0);
    for (int it = 0; it < NIT; it++) {
        int buf = it & 1;
        if (it + 1 < NIT) {
            load_stage(it + 1, buf ^ 1);
            asm volatile("cp.async.wait_group 1;\n");
        } else {
            asm volatile("cp.async.wait_group 0;\n");
        }
        __syncthreads();
#pragma unroll
        for (int kh = 0; kh < 2; kh++) {
            int kk = 16 * kh;
            unsigned a[2][4];
#pragma unroll
            for (int mi = 0; mi < 2; mi++) {
                int r0 = wm * 32 + mi * 16 + g;
                a[mi][0] = *(const unsigned*)&As[buf][r0][kk + 2 * tg];
                a[mi][1] = *(const unsigned*)&As[buf][r0 + 8][kk + 2 * tg];
                a[mi][2] = *(const unsigned*)&As[buf][r0][kk + 2 * tg + 8];
                a[mi][3] = *(const unsigned*)&As[buf][r0 + 8][kk + 2 * tg + 8];
            }
#pragma unroll
            for (int j = 0; j < 7; j++) {
                int nr = wn * 56 + j * 8 + g;
                unsigned b0 = *(const unsigned*)&Bs[buf][nr][kk + 2 * tg];
                unsigned b1 = *(const unsigned*)&Bs[buf][nr][kk + 2 * tg + 8];
#pragma unroll
                for (int mi = 0; mi < 2; mi++) {
                    asm volatile(
                        "mma.sync.aligned.m16n8k16.row.col.f32.bf16.bf16.f32 "
                        "{%0,%1,%2,%3}, {%4,%5,%6,%7}, {%8,%9}, {%0,%1,%2,%3};"
                        : "+f"(acc[mi][j][0]), "+f"(acc[mi][j][1]),
                          "+f"(acc[mi][j][2]), "+f"(acc[mi][j][3])
                        : "r"(a[mi][0]), "r"(a[mi][1]), "r"(a[mi][2]), "r"(a[mi][3]),
                          "r"(b0), "r"(b1));
                }
            }
        }
        __syncthreads();
    }
    // epilogue
#pragma unroll
    for (int mi = 0; mi < 2; mi++) {
        int row0 = bm + wm * 32 + mi * 16 + g;
        int row1 = row0 + 8;
#pragma unroll
        for (int j = 0; j < 7; j++) {
            int col = bn + wn * 56 + j * 8 + 2 * tg;
            float b0 = bias ? bias[col] : 0.f;
            float b1 = bias ? bias[col + 1] : 0.f;
            float2 v0 = make_float2(acc[mi][j][0] + b0, acc[mi][j][1] + b1);
            float2 v1 = make_float2(acc[mi][j][2] + b0, acc[mi][j][3] + b1);
            if (do_relu) {
                v0.x = fmaxf(v0.x, 0.f); v0.y = fmaxf(v0.y, 0.f);
                v1.x = fmaxf(v1.x, 0.f); v1.y = fmaxf(v1.y, 0.f);
            }
            *(float2*)(g_z + (size_t)row0 * DD + col) = v0;
            *(float2*)(g_z + (size_t)row1 * DD + col) = v1;
        }
    }
}

// ---------------- update: warp-per-sample, 4 samples/block ------------------
__global__ __launch_bounds__(128) void update_kernel(const float* __restrict__ X, int col) {
    __shared__ float su[4][280], svh[4][280], sdY[4][784], sP[4][280], ss[4][100], sUS[4][280];
    int w = threadIdx.x >> 5, lane = threadIdx.x & 31;
    int i = blockIdx.x * 4 + w;
    const float* xb = X + (size_t)i * 840;
#pragma unroll
    for (int it = 0; it < 9; it++) {
        int k = lane + 32 * it;
        if (k < 280) { su[w][k] = xb[k]; svh[w][k] = xb[560 + k]; }
    }
#pragma unroll
    for (int it = 0; it < 25; it++) {
        int k = lane + 32 * it;
        if (k < 784) sdY[w][k] = g_z[(size_t)i * DD + k];
    }
#pragma unroll
    for (int it = 0; it < 4; it++) {
        int k = lane + 32 * it;
        if (k < 100) ss[w][k] = g_s[i * 100 + k];
    }
    __syncwarp();
    // P = u^T dY (10x28)
#pragma unroll
    for (int it = 0; it < 9; it++) {
        int k = lane + 32 * it;
        if (k < 280) {
            int a = k / 28, c = k % 28;
            float acc = 0.f;
#pragma unroll
            for (int r = 0; r < 28; r++) acc += su[w][r * 10 + a] * sdY[w][r * 28 + c];
            sP[w][k] = acc;
        }
    }
    __syncwarp();
    // s += H * P vh^T ; write g_s and history
#pragma unroll
    for (int it = 0; it < 4; it++) {
        int k = lane + 32 * it;
        if (k < 100) {
            int a = k / 10, b = k % 10;
            float acc = 0.f;
#pragma unroll
            for (int c = 0; c < 28; c++) acc += sP[w][a * 28 + c] * svh[w][b * 28 + c];
            float sn = ss[w][k] + HCONST * acc;
            ss[w][k] = sn;
            g_s[i * 100 + k] = sn;
            g_shist[(size_t)col * N_SAMP * 100 + (size_t)i * 100 + k] = sn;
        }
    }
    __syncwarp();
    // US = u @ s
#pragma unroll
    for (int it = 0; it < 9; it++) {
        int k = lane + 32 * it;
        if (k < 280) {
            int r = k / 10, b = k % 10;
            float acc = 0.f;
#pragma unroll
            for (int a = 0; a < 10; a++) acc += su[w][r * 10 + a] * ss[w][a * 10 + b];
            sUS[w][k] = acc;
        }
    }
    __syncwarp();
    // x = US @ vh -> bf16 for next GEMM
#pragma unroll
    for (int it = 0; it < 25; it++) {
        int k = lane + 32 * it;
        if (k < 784) {
            int r = k / 28, c = k % 28;
            float acc = 0.f;
#pragma unroll
            for (int b = 0; b < 10; b++) acc += sUS[w][r * 10 + b] * svh[w][b * 28 + c];
            g_xh[(size_t)i * DD + k] = __float2bfloat16(acc);
        }
    }
}

// ---------------- expand: trans[i][k][l] from s_hist -------------------------
__global__ __launch_bounds__(256) void expand_kernel(const float* __restrict__ X,
                                                     float* __restrict__ trans) {
    __shared__ float u[280], vh[280], sall[3300], US[1320], xs[3696];
    int i = blockIdx.x, t = threadIdx.x;
    const float* xb = X + (size_t)i * 840;
    for (int k = t; k < 280; k += 256) { u[k] = xb[k]; vh[k] = xb[560 + k]; }
    for (int k = t; k < 3300; k += 256) {
        int l = k / 100, j = k % 100;
        sall[k] = g_shist[(size_t)l * N_SAMP * 100 + (size_t)i * 100 + j];
    }
    __syncthreads();
    float* base = trans + (size_t)i * (DD * 33);
    for (int ch = 0; ch < 7; ch++) {
        int r0 = ch * 4;
        // US[l][rr][b] for 4 rows
        for (int k = t; k < 1320; k += 256) {
            int l = k / 40, rem = k % 40, rr = rem / 10, b = rem % 10;
            float acc = 0.f;
#pragma unroll
            for (int a = 0; a < 10; a++) acc += u[(r0 + rr) * 10 + a] * sall[l * 100 + a * 10 + b];
            US[k] = acc;
        }
        __syncthreads();
        // xs[l][kk], kk over 112 = 4 rows x 28 cols
        for (int k = t; k < 3696; k += 256) {
            int l = k / 112, kk = k % 112, rr = kk / 28, c = kk % 28;
            float acc = 0.f;
#pragma unroll
            for (int b = 0; b < 10; b++) acc += US[l * 40 + rr * 10 + b] * vh[b * 28 + c];
            xs[k] = acc;
        }
        __syncthreads();
        // coalesced write: element e -> k_local = e/33, l = e%33
        for (int e = t; e < 3696; e += 256) {
            base[ch * 3696 + e] = xs[(e % 33) * 112 + e / 33];
        }
        __syncthreads();
    }
}

// ---------------- classify ---------------------------------------------------
__global__ __launch_bounds__(128) void classify_kernel(const float* __restrict__ X,
                                                       const float* __restrict__ Wc,
                                                       const float* __restrict__ bc,
                                                       float* __restrict__ pred,
                                                       float* __restrict__ cls) {
    __shared__ float u[280], vh[280], s[100], US[280], x[784], lgs[KCLS];
    int i = blockIdx.x, t = threadIdx.x;
    int w = t >> 5, lane = t & 31;
    const float* xb = X + (size_t)i * 840;
    for (int k = t; k < 280; k += 128) { u[k] = xb[k]; vh[k] = xb[560 + k]; }
    for (int k = t; k < 100; k += 128) s[k] = g_s[i * 100 + k];
    __syncthreads();
    for (int k = t; k < 280; k += 128) {
        int r = k / 10, b = k % 10;
        float acc = 0.f;
#pragma unroll
        for (int a = 0; a < 10; a++) acc += u[r * 10 + a] * s[a * 10 + b];
        US[k] = acc;
    }
    __syncthreads();
    for (int k = t; k < 784; k += 128) {
        int r = k / 28, c = k % 28;
        float acc = 0.f;
#pragma unroll
        for (int b = 0; b < 10; b++) acc += US[r * 10 + b] * vh[b * 28 + c];
        x[k] = acc;
    }
    __syncthreads();
    for (int c = w; c < KCLS; c += 4) {
        const float* wr = Wc + (size_t)c * DD;
        float acc = 0.f;
#pragma unroll
        for (int it = 0; it < 25; it++) {
            int k = lane + 32 * it;
            if (k < 784) acc += x[k] * wr[k];
        }
#pragma unroll
        for (int o = 16; o; o >>= 1) acc += __shfl_down_sync(0xffffffffu, acc, o);
        if (lane == 0) lgs[c] = acc + bc[c];
    }
    __syncthreads();
    if (t == 0) {
        float mx = -1e30f;
#pragma unroll
        for (int c = 0; c < KCLS; c++) {
            cls[(size_t)i * KCLS + c] = lgs[c];
            if (lgs[c] > mx) mx = lgs[c];
        }
        float e[KCLS], ssum = 0.f;
#pragma unroll
        for (int c = 0; c < KCLS; c++) { e[c] = expf(lgs[c] - mx); ssum += e[c]; }
        float inv = 1.f / ssum;
#pragma unroll
        for (int c = 0; c < KCLS; c++) pred[(size_t)i * KCLS + c] = e[c] * inv;
    }
}

// ---------------- launcher ---------------------------------------------------
extern "C" void kernel_launch(void* const* d_in, const int* in_sizes, int n_in,
                              void* d_out, int out_size) {
    const float* X  = (const float*)d_in[0];
    const float* W0 = (const float*)d_in[1];
    const float* Ws = (const float*)d_in[2];
    const float* bs = (const float*)d_in[3];
    const float* Wc = (const float*)d_in[4];
    const float* bc = (const float*)d_in[5];
    float* out = (float*)d_out;
    float* pred  = out;
    float* cls   = out + (size_t)N_SAMP * KCLS;
    float* trans = out + (size_t)2 * N_SAMP * KCLS;

    static const __nv_bfloat16* wh_dev = nullptr;
    if (!wh_dev) {
        void* p = nullptr;
        cudaGetSymbolAddress(&p, g_wh);
        wh_dev = (const __nv_bfloat16*)p;
    }

    {
        size_t total = (size_t)33 * DD * DD;
        int blocks = (int)((total / 4 + 255) / 256);
        wcvt_kernel<<<blocks, 256>>>(W0, Ws);
    }
    init_kernel<<<N_SAMP, 256>>>(X);

    dim3 ggrid(DD / GBN, N_SAMP / GBM);   // (7, 16) = 112 blocks
    for (int col = 0; col < 33; col++) {
        const __nv_bfloat16* W = wh_dev + (size_t)col * DD * DD;
        const float* bias = (col > 0) ? (bs + (size_t)(col - 1) * DD) : nullptr;
        gemm_tc_kernel<<<ggrid, 256>>>(W, bias, col > 0 ? 1 : 0);
        update_kernel<<<N_SAMP / 4, 128>>>(X, col);
    }
    expand_kernel<<<N_SAMP, 256>>>(X, trans);
    classify_kernel<<<N_SAMP, 128>>>(X, Wc, bc, pred, cls);
}